// round 4
// baseline (speedup 1.0000x reference)
#include <cuda_runtime.h>
#include <cuda_fp16.h>
#include <cuda_bf16.h>

#define IN_F   2048
#define OUT_F  2048
#define B_ROWS 8192
#define NNZ    1048576

// Dense scratch for the scattered weight matrix (16 MB, static — no allocs).
__device__ float g_W[(size_t)OUT_F * IN_F];

// Runtime input-layout config, decided on-device by sniff_kernel:
//   g_cfg[0] = which candidate buffer is coords (0 or 1)
//   g_cfg[1] = coords are int64 (1) or int32 (0)
//   g_cfg[2] = weights dtype: 0 = fp16, 1 = bf16, 2 = fp32
__device__ int g_cfg[3];

// ---------------------------------------------------------------------------
// Stage 0: sniff the two 1M-element buffers to decide which is coords and
// what dtype the weights are. Deterministic, graph-capturable.
// ---------------------------------------------------------------------------
__global__ void sniff_kernel(const unsigned* p0, const unsigned* p1) {
    __shared__ int cnt[2][4];  // [buf][coord_ok, odd_zero, f16_ok, bf16_ok]
    const int tid = threadIdx.x;
    if (tid < 8) (&cnt[0][0])[tid] = 0;
    __syncthreads();

    const int WORDS = 2048;  // words sampled per buffer (both buffers >= 4MB)
    #pragma unroll
    for (int b = 0; b < 2; ++b) {
        const unsigned* p = b ? p1 : p0;
        int c_coord = 0, c_odd = 0, c_f16 = 0, c_bf16 = 0;
        for (int j = 0; j < WORDS / 256; ++j) {
            int idx = tid * (WORDS / 256) + j;
            unsigned v = p[idx];
            if (v < 4194304u) c_coord++;
            if ((idx & 1) && v == 0u) c_odd++;
            unsigned lo = v & 0xFFFFu, hi = v >> 16;
            float fl = __half2float(__ushort_as_half((unsigned short)lo));
            float fh = __half2float(__ushort_as_half((unsigned short)hi));
            if (fabsf(fl) < 0.5f && fabsf(fl) > 1e-10f &&
                fabsf(fh) < 0.5f && fabsf(fh) > 1e-10f) c_f16++;
            float bl = __uint_as_float(lo << 16);
            float bh = __uint_as_float(hi << 16);
            if (fabsf(bl) < 0.5f && fabsf(bl) > 1e-10f &&
                fabsf(bh) < 0.5f && fabsf(bh) > 1e-10f) c_bf16++;
        }
        atomicAdd(&cnt[b][0], c_coord);
        atomicAdd(&cnt[b][1], c_odd);
        atomicAdd(&cnt[b][2], c_f16);
        atomicAdd(&cnt[b][3], c_bf16);
    }
    __syncthreads();

    if (tid == 0) {
        int ci = (cnt[1][0] > cnt[0][0]) ? 1 : 0;   // coords = buffer where all words < 4M
        g_cfg[0] = ci;
        g_cfg[1] = (cnt[ci][1] >= WORDS / 2 - 8) ? 1 : 0;  // all odd words zero -> int64
        int wb = 1 - ci;
        if      (cnt[wb][2] > (WORDS * 9) / 10) g_cfg[2] = 0;  // fp16
        else if (cnt[wb][3] > (WORDS * 9) / 10) g_cfg[2] = 1;  // bf16
        else                                    g_cfg[2] = 2;  // fp32
    }
}

// ---------------------------------------------------------------------------
// Stage 1: zero W (float4 exact cover)
// ---------------------------------------------------------------------------
__global__ void zero_W_kernel() {
    int i = blockIdx.x * blockDim.x + threadIdx.x;
    reinterpret_cast<float4*>(g_W)[i] = make_float4(0.f, 0.f, 0.f, 0.f);
}

// ---------------------------------------------------------------------------
// Stage 2: COO scatter-accumulate, dtype-dispatched via g_cfg.
// ---------------------------------------------------------------------------
__global__ void scatter_kernel(const void* cand0, const void* cand1) {
    int i = blockIdx.x * blockDim.x + threadIdx.x;
    const void* cbuf = g_cfg[0] ? cand1 : cand0;
    const void* wbuf = g_cfg[0] ? cand0 : cand1;

    long long c = g_cfg[1]
        ? ((const long long*)cbuf)[i]
        : (long long)((const int*)cbuf)[i];

    float w;
    int wt = g_cfg[2];
    if      (wt == 0) w = __half2float(((const __half*)wbuf)[i]);
    else if (wt == 1) w = __bfloat162float(((const __nv_bfloat16*)wbuf)[i]);
    else              w = ((const float*)wbuf)[i];

    if (c >= 0 && c < (long long)OUT_F * IN_F)
        atomicAdd(&g_W[c], w);
}

// ---------------------------------------------------------------------------
// Stage 3: out[b, o] = sum_k x[b, k] * W[o, k]   (A·B^T, both K-major)
// 128x64 block tile, BK=16, 256 threads, 8x4 register tile per thread.
// ---------------------------------------------------------------------------
constexpr int BM = 128;
constexpr int BN = 64;
constexpr int BK = 16;
constexpr int TM = 8;
constexpr int TN = 4;

__global__ __launch_bounds__(256, 2) void gemm_kernel(
    const float* __restrict__ x, float* __restrict__ out) {
    __shared__ float As[BK][BM];   // x tile, transposed to [k][m]
    __shared__ float Bs[BK][BN];   // W tile, transposed to [k][n]

    const int tid = threadIdx.x;
    const int bm = blockIdx.y * BM;
    const int bn = blockIdx.x * BN;

    const int ld_row = tid >> 2;          // 0..63
    const int ld_k   = (tid & 3) * 4;     // 0,4,8,12

    const int tm0 = (tid >> 4) * TM;      // 0..120 step 8
    const int tn0 = (tid & 15) * TN;      // 0..60  step 4

    float acc[TM][TN] = {};

    for (int k0 = 0; k0 < IN_F; k0 += BK) {
        #pragma unroll
        for (int h = 0; h < 2; ++h) {
            int row = ld_row + h * 64;
            float4 v = *reinterpret_cast<const float4*>(
                &x[(size_t)(bm + row) * IN_F + k0 + ld_k]);
            As[ld_k + 0][row] = v.x;
            As[ld_k + 1][row] = v.y;
            As[ld_k + 2][row] = v.z;
            As[ld_k + 3][row] = v.w;
        }
        {
            float4 v = *reinterpret_cast<const float4*>(
                &g_W[(size_t)(bn + ld_row) * IN_F + k0 + ld_k]);
            Bs[ld_k + 0][ld_row] = v.x;
            Bs[ld_k + 1][ld_row] = v.y;
            Bs[ld_k + 2][ld_row] = v.z;
            Bs[ld_k + 3][ld_row] = v.w;
        }
        __syncthreads();

        #pragma unroll
        for (int k = 0; k < BK; ++k) {
            float4 a0 = *reinterpret_cast<const float4*>(&As[k][tm0]);
            float4 a1 = *reinterpret_cast<const float4*>(&As[k][tm0 + 4]);
            float4 bv = *reinterpret_cast<const float4*>(&Bs[k][tn0]);
            float a[TM] = {a0.x, a0.y, a0.z, a0.w, a1.x, a1.y, a1.z, a1.w};
            float b[TN] = {bv.x, bv.y, bv.z, bv.w};
            #pragma unroll
            for (int i = 0; i < TM; ++i)
                #pragma unroll
                for (int j = 0; j < TN; ++j)
                    acc[i][j] = fmaf(a[i], b[j], acc[i][j]);
        }
        __syncthreads();
    }

    #pragma unroll
    for (int i = 0; i < TM; ++i) {
        float4 v = make_float4(acc[i][0], acc[i][1], acc[i][2], acc[i][3]);
        *reinterpret_cast<float4*>(
            &out[(size_t)(bm + tm0 + i) * OUT_F + bn + tn0]) = v;
    }
}

// ---------------------------------------------------------------------------
// Launch. x is identified by size (B*IN_F elements); the other two inputs are
// the 1M-element weights/coords buffers, disambiguated on-device.
// ---------------------------------------------------------------------------
extern "C" void kernel_launch(void* const* d_in, const int* in_sizes, int n_in,
                              void* d_out, int out_size) {
    // Find x = largest input. Remaining two (in order) are the candidates.
    int xi = 0;
    for (int i = 1; i < n_in; ++i)
        if (in_sizes[i] > in_sizes[xi]) xi = i;
    int c0 = -1, c1 = -1;
    for (int i = 0; i < n_in; ++i) {
        if (i == xi) continue;
        if (c0 < 0) c0 = i; else c1 = i;
    }

    const float* x = (const float*)d_in[xi];
    float* out = (float*)d_out;

    sniff_kernel<<<1, 256>>>((const unsigned*)d_in[c0], (const unsigned*)d_in[c1]);
    zero_W_kernel<<<(OUT_F * IN_F / 4) / 256, 256>>>();
    scatter_kernel<<<NNZ / 256, 256>>>(d_in[c0], d_in[c1]);

    dim3 grid(OUT_F / BN, B_ROWS / BM);  // (32, 64)
    gemm_kernel<<<grid, 256>>>(x, out);
}

// round 5
// speedup vs baseline: 1.0012x; 1.0012x over previous
#include <cuda_runtime.h>
#include <cuda_fp16.h>
#include <cuda_bf16.h>

#define IN_F   2048
#define OUT_F  2048
#define B_ROWS 8192
#define NNZ    1048576

// Dense scratch for the scattered weight matrix (16 MB, static — no allocs).
__device__ float g_W[(size_t)OUT_F * IN_F];

// Runtime input-layout config, decided on-device by sniff_kernel:
//   g_cfg[0] = which candidate buffer is coords (0 or 1)
//   g_cfg[1] = coords are int64 (1) or int32 (0)
//   g_cfg[2] = weights dtype: 0 = fp16, 1 = bf16, 2 = fp32
__device__ int g_cfg[3];

// ---------------------------------------------------------------------------
// Stage 0: sniff the two 1M-element buffers to decide which is coords and
// what dtype the weights are. Deterministic, graph-capturable.
// ---------------------------------------------------------------------------
__global__ void sniff_kernel(const unsigned* p0, const unsigned* p1) {
    __shared__ int cnt[2][4];  // [buf][coord_ok, odd_zero, f16_ok, bf16_ok]
    const int tid = threadIdx.x;
    if (tid < 8) (&cnt[0][0])[tid] = 0;
    __syncthreads();

    const int WORDS = 2048;  // words sampled per buffer (both buffers >= 4MB)
    #pragma unroll
    for (int b = 0; b < 2; ++b) {
        const unsigned* p = b ? p1 : p0;
        int c_coord = 0, c_odd = 0, c_f16 = 0, c_bf16 = 0;
        for (int j = 0; j < WORDS / 256; ++j) {
            int idx = tid * (WORDS / 256) + j;
            unsigned v = p[idx];
            if (v < 4194304u) c_coord++;
            if ((idx & 1) && v == 0u) c_odd++;
            unsigned lo = v & 0xFFFFu, hi = v >> 16;
            float fl = __half2float(__ushort_as_half((unsigned short)lo));
            float fh = __half2float(__ushort_as_half((unsigned short)hi));
            if (fabsf(fl) < 0.5f && fabsf(fl) > 1e-10f &&
                fabsf(fh) < 0.5f && fabsf(fh) > 1e-10f) c_f16++;
            float bl = __uint_as_float(lo << 16);
            float bh = __uint_as_float(hi << 16);
            if (fabsf(bl) < 0.5f && fabsf(bl) > 1e-10f &&
                fabsf(bh) < 0.5f && fabsf(bh) > 1e-10f) c_bf16++;
        }
        atomicAdd(&cnt[b][0], c_coord);
        atomicAdd(&cnt[b][1], c_odd);
        atomicAdd(&cnt[b][2], c_f16);
        atomicAdd(&cnt[b][3], c_bf16);
    }
    __syncthreads();

    if (tid == 0) {
        int ci = (cnt[1][0] > cnt[0][0]) ? 1 : 0;   // coords = buffer where all words < 4M
        g_cfg[0] = ci;
        g_cfg[1] = (cnt[ci][1] >= WORDS / 2 - 8) ? 1 : 0;  // all odd words zero -> int64
        int wb = 1 - ci;
        if      (cnt[wb][2] > (WORDS * 9) / 10) g_cfg[2] = 0;  // fp16
        else if (cnt[wb][3] > (WORDS * 9) / 10) g_cfg[2] = 1;  // bf16
        else                                    g_cfg[2] = 2;  // fp32
    }
}

// ---------------------------------------------------------------------------
// Stage 1: zero W (float4 exact cover)
// ---------------------------------------------------------------------------
__global__ void zero_W_kernel() {
    int i = blockIdx.x * blockDim.x + threadIdx.x;
    reinterpret_cast<float4*>(g_W)[i] = make_float4(0.f, 0.f, 0.f, 0.f);
}

// ---------------------------------------------------------------------------
// Stage 2: COO scatter-accumulate, dtype-dispatched via g_cfg.
// ---------------------------------------------------------------------------
__global__ void scatter_kernel(const void* cand0, const void* cand1) {
    int i = blockIdx.x * blockDim.x + threadIdx.x;
    const void* cbuf = g_cfg[0] ? cand1 : cand0;
    const void* wbuf = g_cfg[0] ? cand0 : cand1;

    long long c = g_cfg[1]
        ? ((const long long*)cbuf)[i]
        : (long long)((const int*)cbuf)[i];

    float w;
    int wt = g_cfg[2];
    if      (wt == 0) w = __half2float(((const __half*)wbuf)[i]);
    else if (wt == 1) w = __bfloat162float(((const __nv_bfloat16*)wbuf)[i]);
    else              w = ((const float*)wbuf)[i];

    if (c >= 0 && c < (long long)OUT_F * IN_F)
        atomicAdd(&g_W[c], w);
}

// ---------------------------------------------------------------------------
// Stage 3: out[b, o] = sum_k x[b, k] * W[o, k]   (A·B^T, both K-major)
// 128x64 block tile, BK=16, 256 threads, 8x4 register tile per thread.
// ---------------------------------------------------------------------------
constexpr int BM = 128;
constexpr int BN = 64;
constexpr int BK = 16;
constexpr int TM = 8;
constexpr int TN = 4;

__global__ __launch_bounds__(256, 2) void gemm_kernel(
    const float* __restrict__ x, float* __restrict__ out) {
    __shared__ float As[BK][BM];   // x tile, transposed to [k][m]
    __shared__ float Bs[BK][BN];   // W tile, transposed to [k][n]

    const int tid = threadIdx.x;
    const int bm = blockIdx.y * BM;
    const int bn = blockIdx.x * BN;

    const int ld_row = tid >> 2;          // 0..63
    const int ld_k   = (tid & 3) * 4;     // 0,4,8,12

    const int tm0 = (tid >> 4) * TM;      // 0..120 step 8
    const int tn0 = (tid & 15) * TN;      // 0..60  step 4

    float acc[TM][TN] = {};

    for (int k0 = 0; k0 < IN_F; k0 += BK) {
        #pragma unroll
        for (int h = 0; h < 2; ++h) {
            int row = ld_row + h * 64;
            float4 v = *reinterpret_cast<const float4*>(
                &x[(size_t)(bm + row) * IN_F + k0 + ld_k]);
            As[ld_k + 0][row] = v.x;
            As[ld_k + 1][row] = v.y;
            As[ld_k + 2][row] = v.z;
            As[ld_k + 3][row] = v.w;
        }
        {
            float4 v = *reinterpret_cast<const float4*>(
                &g_W[(size_t)(bn + ld_row) * IN_F + k0 + ld_k]);
            Bs[ld_k + 0][ld_row] = v.x;
            Bs[ld_k + 1][ld_row] = v.y;
            Bs[ld_k + 2][ld_row] = v.z;
            Bs[ld_k + 3][ld_row] = v.w;
        }
        __syncthreads();

        #pragma unroll
        for (int k = 0; k < BK; ++k) {
            float4 a0 = *reinterpret_cast<const float4*>(&As[k][tm0]);
            float4 a1 = *reinterpret_cast<const float4*>(&As[k][tm0 + 4]);
            float4 bv = *reinterpret_cast<const float4*>(&Bs[k][tn0]);
            float a[TM] = {a0.x, a0.y, a0.z, a0.w, a1.x, a1.y, a1.z, a1.w};
            float b[TN] = {bv.x, bv.y, bv.z, bv.w};
            #pragma unroll
            for (int i = 0; i < TM; ++i)
                #pragma unroll
                for (int j = 0; j < TN; ++j)
                    acc[i][j] = fmaf(a[i], b[j], acc[i][j]);
        }
        __syncthreads();
    }

    #pragma unroll
    for (int i = 0; i < TM; ++i) {
        float4 v = make_float4(acc[i][0], acc[i][1], acc[i][2], acc[i][3]);
        *reinterpret_cast<float4*>(
            &out[(size_t)(bm + tm0 + i) * OUT_F + bn + tn0]) = v;
    }
}

// ---------------------------------------------------------------------------
// Launch. x is identified by size (B*IN_F elements); the other two inputs are
// the 1M-element weights/coords buffers, disambiguated on-device.
// ---------------------------------------------------------------------------
extern "C" void kernel_launch(void* const* d_in, const int* in_sizes, int n_in,
                              void* d_out, int out_size) {
    // Find x = largest input. Remaining two (in order) are the candidates.
    int xi = 0;
    for (int i = 1; i < n_in; ++i)
        if (in_sizes[i] > in_sizes[xi]) xi = i;
    int c0 = -1, c1 = -1;
    for (int i = 0; i < n_in; ++i) {
        if (i == xi) continue;
        if (c0 < 0) c0 = i; else c1 = i;
    }

    const float* x = (const float*)d_in[xi];
    float* out = (float*)d_out;

    sniff_kernel<<<1, 256>>>((const unsigned*)d_in[c0], (const unsigned*)d_in[c1]);
    zero_W_kernel<<<(OUT_F * IN_F / 4) / 256, 256>>>();
    scatter_kernel<<<NNZ / 256, 256>>>(d_in[c0], d_in[c1]);

    dim3 grid(OUT_F / BN, B_ROWS / BM);  // (32, 64)
    gemm_kernel<<<grid, 256>>>(x, out);
}